// round 16
// baseline (speedup 1.0000x reference)
#include <cuda_runtime.h>
#include <cuda_bf16.h>
#include <cstdint>

#define N_NODES 50000
#define N_EDGES 800000
#define IN_CH 64
#define OUT_CH 64
#define N_REL 8
#define N_BASES 4
#define XB_COLS 256            // 4 bases * 64 out
#define GEMM_N 320             // 256 xb cols + 64 root cols
#define PAD 64                 // slots per node bucket (P(deg>=64) ~ e^-126)
#define N_SLOTS (N_NODES * PAD)

// Scratch (__device__ globals). g_cnt relies on zero-init at module load;
// edge_kernel<CLEAN=true> re-zeroes it every launch (self-cleaning invariant).
__device__ float4 g_xb4[(size_t)N_NODES * XB_COLS / 4];  // node-major [N, 256]
__device__ float4 g_agg04[(size_t)N_NODES * OUT_CH / 4]; // layer-0 accumulator
__device__ uint4  g_Bhi4[2 * GEMM_N * 64 * 2 / 16];      // [2][320][64] bf16 hi
__device__ uint4  g_Blo4[2 * GEMM_N * 64 * 2 / 16];      // [2][320][64] bf16 lo
// padded direct-placement buckets (src-grouped, no sort/scan needed)
__device__ int    g_cnt[N_NODES];      // per-src degree counter (0 outside window)
__device__ int2   g_dp[N_SLOTS];       // {dst, perm|invalid_bit} per slot
__device__ float4 g_ebS0[N_SLOTS];     // eb layer 0 per slot
__device__ float4 g_ebS1[N_SLOTS];     // eb layer 1 per slot

// ---------------------------------------------------------------------------
// Helpers (arch-generic PTX only: ldmatrix + mma.sync, sm_80+)
// ---------------------------------------------------------------------------
__device__ __forceinline__ uint32_t smem_u32(const void* p) {
    uint32_t a;
    asm("{ .reg .u64 t; cvta.to.shared.u64 t, %1; cvt.u32.u64 %0, t; }"
        : "=r"(a) : "l"(p));
    return a;
}
__device__ __forceinline__ void ldsm_x4(uint32_t* r, uint32_t addr) {
    asm volatile("ldmatrix.sync.aligned.m8n8.x4.shared.b16 {%0,%1,%2,%3}, [%4];"
                 : "=r"(r[0]), "=r"(r[1]), "=r"(r[2]), "=r"(r[3]) : "r"(addr));
}
__device__ __forceinline__ void mma16816(float* c, const uint32_t* a, const uint32_t* b) {
    asm volatile(
        "mma.sync.aligned.m16n8k16.row.col.f32.bf16.bf16.f32 "
        "{%0,%1,%2,%3}, {%4,%5,%6,%7}, {%8,%9}, {%0,%1,%2,%3};"
        : "+f"(c[0]), "+f"(c[1]), "+f"(c[2]), "+f"(c[3])
        : "r"(a[0]), "r"(a[1]), "r"(a[2]), "r"(a[3]), "r"(b[0]), "r"(b[1]));
}

// ---------------------------------------------------------------------------
// Kernel 0: split weights into bf16 hi/lo
// ---------------------------------------------------------------------------
__global__ void __launch_bounds__(256)
bprep_kernel(const float* __restrict__ basis,   // [2,4,64,64]
             const float* __restrict__ root) {  // [2,64,64]
    int idx = blockIdx.x * blockDim.x + threadIdx.x;
    if (idx >= 2 * GEMM_N * 64) return;
    int l = idx / (GEMM_N * 64);
    int rem = idx - l * (GEMM_N * 64);
    int n = rem >> 6;
    int k = rem & 63;
    float v = (n < 256) ? basis[(((l * 4) + (n >> 6)) * 64 + k) * 64 + (n & 63)]
                        : root[(l * 64 + k) * 64 + (n - 256)];
    __nv_bfloat16 hb = __float2bfloat16(v);
    __nv_bfloat16 lb = __float2bfloat16(v - __bfloat162float(hb));
    reinterpret_cast<unsigned short*>(g_Bhi4)[idx] = __bfloat16_as_ushort(hb);
    reinterpret_cast<unsigned short*>(g_Blo4)[idx] = __bfloat16_as_ushort(lb);
}

// ---------------------------------------------------------------------------
// Kernel 1: direct-placement scatter + fused LAYER-0 eb projection.
// slot = src*PAD + rank. No count/scan needed. g_cnt zero at entry
// (module-load zero-init, then edge_kernel<true> restores it each call).
// ---------------------------------------------------------------------------
__global__ void __launch_bounds__(256)
scatter_pad_kernel(const int* __restrict__ ei,     // [2, E] int32
                   const float* __restrict__ ea,   // [E, 8]
                   const float* __restrict__ att0) {// [8, 4] layer 0
    __shared__ float sA[N_REL][N_BASES];
    if (threadIdx.x < N_REL * N_BASES)
        reinterpret_cast<float*>(sA)[threadIdx.x] = att0[threadIdx.x];
    __syncthreads();

    int e = blockIdx.x * 256 + threadIdx.x;
    if (e >= N_EDGES) return;
    int src = ei[e];
    int dst = ei[N_EDGES + e];
    bool valid = ((unsigned)src < N_NODES) && ((unsigned)dst < N_NODES);
    if ((unsigned)src >= N_NODES) src = 0;
    if ((unsigned)dst >= N_NODES) dst = 0;

    const float4* ep = reinterpret_cast<const float4*>(ea + (size_t)e * N_REL);
    float4 a0 = ep[0];
    float4 a1 = ep[1];
    float r[8] = {a0.x, a0.y, a0.z, a0.w, a1.x, a1.y, a1.z, a1.w};

    float4 o0 = make_float4(0.f, 0.f, 0.f, 0.f);
#pragma unroll
    for (int k = 0; k < N_REL; k++) {
        o0.x = fmaf(r[k], sA[k][0], o0.x);
        o0.y = fmaf(r[k], sA[k][1], o0.y);
        o0.z = fmaf(r[k], sA[k][2], o0.z);
        o0.w = fmaf(r[k], sA[k][3], o0.w);
    }
    if (!valid) o0 = make_float4(0.f, 0.f, 0.f, 0.f);

    int rank = atomicAdd(&g_cnt[src], 1);
    if (rank < PAD) {                          // statistically always true
        int slot = src * PAD + rank;
        g_dp[slot] = make_int2(dst, valid ? e : (e | (int)0x80000000));
        g_ebS0[slot] = o0;
    }
}

// ---------------------------------------------------------------------------
// Kernel 2: layer-1 eb projection over padded slots (valid ones only).
// Runs after scatter; overlaps gemm0 tail / edge0 on the timeline.
// ---------------------------------------------------------------------------
__global__ void __launch_bounds__(256)
ebg1_kernel(const float* __restrict__ ea,    // [E, 8]
            const float* __restrict__ att1) {// [8, 4] layer 1
    __shared__ float sA[N_REL][N_BASES];
    if (threadIdx.x < N_REL * N_BASES)
        reinterpret_cast<float*>(sA)[threadIdx.x] = att1[threadIdx.x];
    __syncthreads();

    int pos = blockIdx.x * 256 + threadIdx.x;
    if (pos >= N_SLOTS) return;
    int n = pos >> 6;              // PAD = 64
    int rk = pos & (PAD - 1);
    int cnt = g_cnt[n];
    if (rk >= (cnt < PAD ? cnt : PAD)) return;

    int raw = g_dp[pos].y;
    int e = raw & 0x7FFFFFFF;
    bool valid = (raw >= 0);

    const float4* ep = reinterpret_cast<const float4*>(ea + (size_t)e * N_REL);
    float4 a0 = ep[0];
    float4 a1 = ep[1];
    float r[8] = {a0.x, a0.y, a0.z, a0.w, a1.x, a1.y, a1.z, a1.w};

    float4 o = make_float4(0.f, 0.f, 0.f, 0.f);
#pragma unroll
    for (int k = 0; k < N_REL; k++) {
        o.x = fmaf(r[k], sA[k][0], o.x);
        o.y = fmaf(r[k], sA[k][1], o.y);
        o.z = fmaf(r[k], sA[k][2], o.z);
        o.w = fmaf(r[k], sA[k][3], o.w);
    }
    if (!valid) o = make_float4(0.f, 0.f, 0.f, 0.f);
    g_ebS1[pos] = o;
}

// ---------------------------------------------------------------------------
// Kernel 3: node GEMM on tensor cores via mma.sync, bf16x3 split. (proven)
// ---------------------------------------------------------------------------
#define LDA 144
#define SM_AHI 0
#define SM_ALO 18432
#define SM_BHI 36864
#define SM_BLO 46080
#define SMEM_BYTES 55296

template <bool RELU>
__global__ void __launch_bounds__(256)
gemm_mma(const float* __restrict__ h,
         const uint4* __restrict__ Bhi,    // [320][64] bf16 (this layer)
         const uint4* __restrict__ Blo,
         const float* __restrict__ bias,
         float* __restrict__ agg) {
    extern __shared__ char smem[];
    const uint32_t sb = smem_u32(smem);
    const int tid = threadIdx.x;
    const int wid = tid >> 5;
    const int lid = tid & 31;
    const int nodeBase = blockIdx.x * 128;
    float* xb = reinterpret_cast<float*>(g_xb4);

    // ---- Convert A rows to bf16 hi/lo into padded smem ----
    if (tid < 128) {
        int n = nodeBase + tid;
        const float4* hp = reinterpret_cast<const float4*>(h + (size_t)n * IN_CH);
        bool valid = (n < N_NODES);
#pragma unroll
        for (int j = 0; j < 8; j++) {
            float f[8];
            if (valid) {
                float4 a = hp[2 * j];
                float4 b = hp[2 * j + 1];
                f[0] = a.x; f[1] = a.y; f[2] = a.z; f[3] = a.w;
                f[4] = b.x; f[5] = b.y; f[6] = b.z; f[7] = b.w;
            } else {
#pragma unroll
                for (int t = 0; t < 8; t++) f[t] = 0.f;
            }
            uint32_t hw[4], lw[4];
#pragma unroll
            for (int q = 0; q < 4; q++) {
                float v0 = f[2 * q], v1 = f[2 * q + 1];
                if (RELU) { v0 = fmaxf(v0, 0.f); v1 = fmaxf(v1, 0.f); }
                __nv_bfloat16 h0 = __float2bfloat16(v0);
                __nv_bfloat16 h1 = __float2bfloat16(v1);
                __nv_bfloat16 l0 = __float2bfloat16(v0 - __bfloat162float(h0));
                __nv_bfloat16 l1 = __float2bfloat16(v1 - __bfloat162float(h1));
                hw[q] = (uint32_t)__bfloat16_as_ushort(h0) |
                        ((uint32_t)__bfloat16_as_ushort(h1) << 16);
                lw[q] = (uint32_t)__bfloat16_as_ushort(l0) |
                        ((uint32_t)__bfloat16_as_ushort(l1) << 16);
            }
            *reinterpret_cast<uint4*>(smem + SM_AHI + tid * LDA + j * 16) =
                make_uint4(hw[0], hw[1], hw[2], hw[3]);
            *reinterpret_cast<uint4*>(smem + SM_ALO + tid * LDA + j * 16) =
                make_uint4(lw[0], lw[1], lw[2], lw[3]);
        }
    }
    __syncthreads();

    // ---- Hoist A fragments ----
    uint32_t ahi[4][4], alo[4][4];
    {
        uint32_t aoff = (uint32_t)(wid * 16 + (lid & 15)) * LDA + ((lid >> 4) << 4);
#pragma unroll
        for (int ks = 0; ks < 4; ks++) {
            ldsm_x4(ahi[ks], sb + SM_AHI + aoff + ks * 32);
            ldsm_x4(alo[ks], sb + SM_ALO + aoff + ks * 32);
        }
    }

    const uint32_t bLane = (uint32_t)((lid & 7) + ((lid >> 4) << 3)) * LDA +
                           (((lid >> 3) & 1) << 4);

#pragma unroll 1
    for (int nt = 0; nt < 5; nt++) {
        if (nt) __syncthreads();
#pragma unroll
        for (int u = tid; u < 512; u += 256) {
            int row = u >> 3;
            int j = u & 7;
            uint32_t off = (uint32_t)row * LDA + j * 16;
            int src = (nt * 64 + row) * 8 + j;
            *reinterpret_cast<uint4*>(smem + SM_BHI + off) = Bhi[src];
            *reinterpret_cast<uint4*>(smem + SM_BLO + off) = Blo[src];
        }
        __syncthreads();

        float acc[8][4];
#pragma unroll
        for (int t = 0; t < 8; t++)
#pragma unroll
            for (int q = 0; q < 4; q++) acc[t][q] = 0.f;

#pragma unroll
        for (int np = 0; np < 4; np++) {
            uint32_t bbase = (uint32_t)(np * 16) * LDA + bLane;
#pragma unroll
            for (int ks = 0; ks < 4; ks++) {
                uint32_t bh[4], bl[4];
                ldsm_x4(bh, sb + SM_BHI + bbase + ks * 32);
                ldsm_x4(bl, sb + SM_BLO + bbase + ks * 32);
                mma16816(acc[np * 2 + 0], ahi[ks], bh + 0);
                mma16816(acc[np * 2 + 1], ahi[ks], bh + 2);
                mma16816(acc[np * 2 + 0], ahi[ks], bl + 0);
                mma16816(acc[np * 2 + 1], ahi[ks], bl + 2);
                mma16816(acc[np * 2 + 0], alo[ks], bh + 0);
                mma16816(acc[np * 2 + 1], alo[ks], bh + 2);
            }
        }

        int r0 = nodeBase + wid * 16 + (lid >> 2);
        int cOff = 2 * (lid & 3);
#pragma unroll
        for (int t = 0; t < 8; t++) {
            int col = nt * 64 + t * 8 + cOff;
            if (nt < 4) {
                if (r0 < N_NODES)
                    *reinterpret_cast<float2*>(xb + (size_t)r0 * XB_COLS + col) =
                        make_float2(acc[t][0], acc[t][1]);
                if (r0 + 8 < N_NODES)
                    *reinterpret_cast<float2*>(xb + (size_t)(r0 + 8) * XB_COLS + col) =
                        make_float2(acc[t][2], acc[t][3]);
            } else {
                int oc = col - 256;
                float b0 = __ldg(bias + oc);
                float b1 = __ldg(bias + oc + 1);
                if (r0 < N_NODES)
                    *reinterpret_cast<float2*>(agg + (size_t)r0 * OUT_CH + oc) =
                        make_float2(acc[t][0] + b0, acc[t][1] + b1);
                if (r0 + 8 < N_NODES)
                    *reinterpret_cast<float2*>(agg + (size_t)(r0 + 8) * OUT_CH + oc) =
                        make_float2(acc[t][2] + b0, acc[t][3] + b1);
            }
        }
    }
}

// ---------------------------------------------------------------------------
// Kernel 4: SRC-RUN edge kernel over padded buckets. Half-warp per node.
// CLEAN=true (layer-1/last pass) zeroes g_cnt after reading it — restores the
// zero-invariant for the next graph replay. (Lane-0 store after all lanes'
// loads of the same instruction — no race within the owning half-warp.)
// ---------------------------------------------------------------------------
template <bool CLEAN>
__global__ void __launch_bounds__(256)
edge_kernel(const float4* __restrict__ eb,      // per-slot basis weights
            float* __restrict__ agg) {
    int t = blockIdx.x * blockDim.x + threadIdx.x;
    int n = t >> 4;
    int l = t & 15;
    if (n >= N_NODES) return;

    int cnt = g_cnt[n];
    if (CLEAN) {
        if (l == 0) g_cnt[n] = 0;
    }
    if (cnt > PAD) cnt = PAD;
    if (cnt == 0) return;

    const float4* xs = g_xb4 + (size_t)n * (XB_COLS / 4);
    float4 v0 = xs[0 * 16 + l];
    float4 v1 = xs[1 * 16 + l];
    float4 v2 = xs[2 * 16 + l];
    float4 v3 = xs[3 * 16 + l];

    int base = n * PAD;
    for (int r = 0; r < cnt; r++) {
        float4 w = __ldg(eb + base + r);   // broadcast across 16 lanes
        int dst = __ldg(&g_dp[base + r].x);

        float4 acc;
        acc.x = fmaf(w.x, v0.x, fmaf(w.y, v1.x, fmaf(w.z, v2.x, w.w * v3.x)));
        acc.y = fmaf(w.x, v0.y, fmaf(w.y, v1.y, fmaf(w.z, v2.y, w.w * v3.y)));
        acc.z = fmaf(w.x, v0.z, fmaf(w.y, v1.z, fmaf(w.z, v2.z, w.w * v3.z)));
        acc.w = fmaf(w.x, v0.w, fmaf(w.y, v1.w, fmaf(w.z, v2.w, w.w * v3.w)));

        float* out = agg + (size_t)dst * OUT_CH + l * 4;
        asm volatile("red.global.add.v4.f32 [%0], {%1, %2, %3, %4};"
                     :: "l"(out), "f"(acc.x), "f"(acc.y), "f"(acc.z), "f"(acc.w)
                     : "memory");
    }
}

// ---------------------------------------------------------------------------
// Launch — forked capture: bucket scatter on side stream, GEMM on default.
// ---------------------------------------------------------------------------
extern "C" void kernel_launch(void* const* d_in, const int* in_sizes, int n_in,
                              void* d_out, int out_size) {
    const float* x        = (const float*)d_in[0];
    const int* ei         = (const int*)d_in[1];     // int32
    const float* ea       = (const float*)d_in[2];
    const float* basis    = (const float*)d_in[3];   // [2, 4, 64, 64]
    const float* att      = (const float*)d_in[4];   // [2, 8, 4]
    const float* root     = (const float*)d_in[5];   // [2, 64, 64]
    const float* bias     = (const float*)d_in[6];   // [2, 64]
    float* out            = (float*)d_out;

    void* p = nullptr;
    cudaGetSymbolAddress(&p, g_agg04);
    float* agg0 = (float*)p;
    cudaGetSymbolAddress(&p, g_ebS0);
    float4* ebS0 = (float4*)p;
    cudaGetSymbolAddress(&p, g_ebS1);
    float4* ebS1 = (float4*)p;
    cudaGetSymbolAddress(&p, g_Bhi4);
    const uint4* Bhi = (const uint4*)p;
    cudaGetSymbolAddress(&p, g_Blo4);
    const uint4* Blo = (const uint4*)p;

    cudaFuncSetAttribute(gemm_mma<false>, cudaFuncAttributeMaxDynamicSharedMemorySize, SMEM_BYTES);
    cudaFuncSetAttribute(gemm_mma<true>,  cudaFuncAttributeMaxDynamicSharedMemorySize, SMEM_BYTES);

    // One-time stream/event setup (host resources only; no device memory)
    static cudaStream_t s2 = nullptr;
    static cudaEvent_t evF = nullptr, evA = nullptr, evB = nullptr;
    if (s2 == nullptr) {
        cudaStreamCreateWithFlags(&s2, cudaStreamNonBlocking);
        cudaEventCreateWithFlags(&evF, cudaEventDisableTiming);
        cudaEventCreateWithFlags(&evA, cudaEventDisableTiming);
        cudaEventCreateWithFlags(&evB, cudaEventDisableTiming);
    }

    const int eBlocks     = (N_EDGES + 255) / 256;          // 3125
    const int slotBlocks  = (N_SLOTS + 255) / 256;          // 12500
    const int gemmBlocks  = (N_NODES + 127) / 128;          // 391
    const int nodeBlocks  = (N_NODES * 16 + 255) / 256;     // 3125
    const int bprepBlocks = (2 * GEMM_N * 64 + 255) / 256;  // 160

    const float* att1  = att + N_REL * N_BASES;
    const float* bias1 = bias + OUT_CH;
    const int layerStride = GEMM_N * 64 * 2 / 16;   // uint4 per layer

    // ---- Fork: side stream joins the capture ----
    cudaEventRecord(evF, 0);
    cudaStreamWaitEvent(s2, evF, 0);

    // Side stream: one-kernel bucket scatter (+ fused eb0), then layer-1 eb
    scatter_pad_kernel<<<eBlocks, 256, 0, s2>>>(ei, ea, att);
    cudaEventRecord(evA, s2);
    ebg1_kernel<<<slotBlocks, 256, 0, s2>>>(ea, att1);   // overlaps gemm0/edge0
    cudaEventRecord(evB, s2);

    // Default stream: weight prep + layer-0 GEMM (independent of scatter)
    bprep_kernel<<<bprepBlocks, 256>>>(basis, root);
    gemm_mma<false><<<gemmBlocks, 256, SMEM_BYTES>>>(x, Bhi, Blo, bias, agg0);

    // Join A: edge0 needs buckets + gemm0 output
    cudaStreamWaitEvent(0, evA, 0);
    edge_kernel<false><<<nodeBlocks, 256>>>(ebS0, agg0);

    // Layer 1
    gemm_mma<true><<<gemmBlocks, 256, SMEM_BYTES>>>(agg0, Bhi + layerStride,
                                                    Blo + layerStride, bias1, out);
    cudaStreamWaitEvent(0, evB, 0);
    edge_kernel<true><<<nodeBlocks, 256>>>(ebS1, out);   // CLEAN: re-zero g_cnt
}

// round 17
// speedup vs baseline: 1.2048x; 1.2048x over previous
#include <cuda_runtime.h>
#include <cuda_bf16.h>
#include <cstdint>

#define N_NODES 50000
#define N_EDGES 800000
#define IN_CH 64
#define OUT_CH 64
#define N_REL 8
#define N_BASES 4
#define XB_COLS 256            // 4 bases * 64 out
#define GEMM_N 320             // 256 xb cols + 64 root cols
#define NBINS 50176            // 196 * 256 (padded bins)
#define NBLK 196

// Scratch (__device__ globals). g_hist relies on zero-init at module load;
// scan1 re-zeroes it every launch (self-cleaning invariant).
__device__ float4 g_xb4[(size_t)N_NODES * XB_COLS / 4];  // node-major [N, 256]
__device__ float4 g_agg04[(size_t)N_NODES * OUT_CH / 4]; // layer-0 accumulator
__device__ uint4  g_Bhi4[2 * GEMM_N * 64 * 2 / 16];      // [2][320][64] bf16 hi
__device__ uint4  g_Blo4[2 * GEMM_N * 64 * 2 / 16];      // [2][320][64] bf16 lo
// counting sort by SRC (CSR-style out-edge runs)
__device__ int    g_hist[NBINS];       // ALWAYS zero outside count->scan1 window
__device__ int    g_lex[NBINS];        // per-block local exclusive prefix
__device__ int    g_bsumRaw[256];      // per-block totals
__device__ int    g_start[NBINS + 1];  // global exclusive prefix (run starts)
__device__ int    g_cursor[NBINS];     // scatter cursors
__device__ int2   g_dp[N_EDGES];       // {dst, perm|invalid_bit}, src-sorted
__device__ float4 g_ebS0[N_EDGES];     // eb layer 0, src-sorted
__device__ float4 g_ebS1[N_EDGES];     // eb layer 1, src-sorted

// ---------------------------------------------------------------------------
// Helpers (arch-generic PTX only: ldmatrix + mma.sync, sm_80+)
// ---------------------------------------------------------------------------
__device__ __forceinline__ uint32_t smem_u32(const void* p) {
    uint32_t a;
    asm("{ .reg .u64 t; cvta.to.shared.u64 t, %1; cvt.u32.u64 %0, t; }"
        : "=r"(a) : "l"(p));
    return a;
}
__device__ __forceinline__ void ldsm_x4(uint32_t* r, uint32_t addr) {
    asm volatile("ldmatrix.sync.aligned.m8n8.x4.shared.b16 {%0,%1,%2,%3}, [%4];"
                 : "=r"(r[0]), "=r"(r[1]), "=r"(r[2]), "=r"(r[3]) : "r"(addr));
}
__device__ __forceinline__ void mma16816(float* c, const uint32_t* a, const uint32_t* b) {
    asm volatile(
        "mma.sync.aligned.m16n8k16.row.col.f32.bf16.bf16.f32 "
        "{%0,%1,%2,%3}, {%4,%5,%6,%7}, {%8,%9}, {%0,%1,%2,%3};"
        : "+f"(c[0]), "+f"(c[1]), "+f"(c[2]), "+f"(c[3])
        : "r"(a[0]), "r"(a[1]), "r"(a[2]), "r"(a[3]), "r"(b[0]), "r"(b[1]));
}

// ---------------------------------------------------------------------------
// Kernel 0: split weights into bf16 hi/lo
// ---------------------------------------------------------------------------
__global__ void __launch_bounds__(256)
bprep_kernel(const float* __restrict__ basis,   // [2,4,64,64]
             const float* __restrict__ root) {  // [2,64,64]
    int idx = blockIdx.x * blockDim.x + threadIdx.x;
    if (idx >= 2 * GEMM_N * 64) return;
    int l = idx / (GEMM_N * 64);
    int rem = idx - l * (GEMM_N * 64);
    int n = rem >> 6;
    int k = rem & 63;
    float v = (n < 256) ? basis[(((l * 4) + (n >> 6)) * 64 + k) * 64 + (n & 63)]
                        : root[(l * 64 + k) * 64 + (n - 256)];
    __nv_bfloat16 hb = __float2bfloat16(v);
    __nv_bfloat16 lb = __float2bfloat16(v - __bfloat162float(hb));
    reinterpret_cast<unsigned short*>(g_Bhi4)[idx] = __bfloat16_as_ushort(hb);
    reinterpret_cast<unsigned short*>(g_Blo4)[idx] = __bfloat16_as_ushort(lb);
}

// ---------------------------------------------------------------------------
// Kernel 1: count by SRC (g_hist guaranteed zero at entry)
// ---------------------------------------------------------------------------
__global__ void __launch_bounds__(256)
count_kernel(const int* __restrict__ ei) {
    int e = blockIdx.x * 256 + threadIdx.x;
    if (e >= N_EDGES) return;
    int src = ei[e];
    if ((unsigned)src >= N_NODES) src = 0;   // defensive clamp (consistent w/ scatter)
    atomicAdd(&g_hist[src], 1);
}

// ---------------------------------------------------------------------------
// Kernel 2: per-block exclusive scan -> g_lex, block totals; re-zero g_hist
// ---------------------------------------------------------------------------
__global__ void __launch_bounds__(256)
scan1_kernel() {
    __shared__ int s[256];
    int i = blockIdx.x * 256 + threadIdx.x;
    int v = g_hist[i];
    g_hist[i] = 0;                            // self-clean
    s[threadIdx.x] = v;
    __syncthreads();
#pragma unroll
    for (int off = 1; off < 256; off <<= 1) {
        int t = (threadIdx.x >= off) ? s[threadIdx.x - off] : 0;
        __syncthreads();
        s[threadIdx.x] += t;
        __syncthreads();
    }
    g_lex[i] = s[threadIdx.x] - v;            // exclusive (local)
    if (threadIdx.x == 255) g_bsumRaw[blockIdx.x] = s[255];
}

// ---------------------------------------------------------------------------
// Kernel 3: start/cursor; each block redundantly reduces block totals
// ---------------------------------------------------------------------------
__global__ void __launch_bounds__(256)
scan3_kernel() {
    __shared__ int red[256];
    int b = blockIdx.x;
    int t = threadIdx.x;
    red[t] = (t < b && t < NBLK) ? g_bsumRaw[t] : 0;
    __syncthreads();
#pragma unroll
    for (int off = 128; off > 0; off >>= 1) {
        if (t < off) red[t] += red[t + off];
        __syncthreads();
    }
    int offset = red[0];
    int i = b * 256 + t;
    int s = g_lex[i] + offset;
    g_start[i] = s;
    g_cursor[i] = s;
    if (i == 0) g_start[NBINS] = N_EDGES;
}

// ---------------------------------------------------------------------------
// Kernel 4: scatter {dst,perm} (single int2 store) + fused LAYER-0 eb.
// Random stores per edge: dp 8B + ebS0 16B (was 3 sectors, now 2).
// ---------------------------------------------------------------------------
__global__ void __launch_bounds__(256)
scatter_eb0_kernel(const int* __restrict__ ei,
                   const float* __restrict__ ea,    // [E, 8]
                   const float* __restrict__ att0) {// [8, 4] layer 0
    __shared__ float sA[N_REL][N_BASES];
    if (threadIdx.x < N_REL * N_BASES)
        reinterpret_cast<float*>(sA)[threadIdx.x] = att0[threadIdx.x];
    __syncthreads();

    int e = blockIdx.x * 256 + threadIdx.x;
    if (e >= N_EDGES) return;
    int src = ei[e];
    int dst = ei[N_EDGES + e];
    bool valid = ((unsigned)src < N_NODES) && ((unsigned)dst < N_NODES);
    if ((unsigned)src >= N_NODES) src = 0;
    if ((unsigned)dst >= N_NODES) dst = 0;

    const float4* ep = reinterpret_cast<const float4*>(ea + (size_t)e * N_REL);
    float4 a0 = ep[0];
    float4 a1 = ep[1];
    float r[8] = {a0.x, a0.y, a0.z, a0.w, a1.x, a1.y, a1.z, a1.w};

    float4 o0 = make_float4(0.f, 0.f, 0.f, 0.f);
#pragma unroll
    for (int k = 0; k < N_REL; k++) {
        o0.x = fmaf(r[k], sA[k][0], o0.x);
        o0.y = fmaf(r[k], sA[k][1], o0.y);
        o0.z = fmaf(r[k], sA[k][2], o0.z);
        o0.w = fmaf(r[k], sA[k][3], o0.w);
    }
    if (!valid) o0 = make_float4(0.f, 0.f, 0.f, 0.f);

    int pos = atomicAdd(&g_cursor[src], 1);
    g_dp[pos] = make_int2(dst, valid ? e : (e | (int)0x80000000));
    g_ebS0[pos] = o0;
}

// ---------------------------------------------------------------------------
// Kernel 5: one-layer eb projection into sorted slots (layer 1; overlaps edge0)
// ---------------------------------------------------------------------------
__global__ void __launch_bounds__(256)
eb_gather_kernel(const float* __restrict__ ea,   // [E, 8]
                 const float* __restrict__ att,  // [8, 4] (this layer)
                 float4* __restrict__ ebS) {
    __shared__ float sA[N_REL][N_BASES];
    if (threadIdx.x < N_REL * N_BASES)
        reinterpret_cast<float*>(sA)[threadIdx.x] = att[threadIdx.x];
    __syncthreads();

    int pos = blockIdx.x * 256 + threadIdx.x;
    if (pos >= N_EDGES) return;

    int raw = g_dp[pos].y;
    int e = raw & 0x7FFFFFFF;
    bool valid = (raw >= 0);

    const float4* ep = reinterpret_cast<const float4*>(ea + (size_t)e * N_REL);
    float4 a0 = ep[0];
    float4 a1 = ep[1];
    float r[8] = {a0.x, a0.y, a0.z, a0.w, a1.x, a1.y, a1.z, a1.w};

    float4 o = make_float4(0.f, 0.f, 0.f, 0.f);
#pragma unroll
    for (int k = 0; k < N_REL; k++) {
        o.x = fmaf(r[k], sA[k][0], o.x);
        o.y = fmaf(r[k], sA[k][1], o.y);
        o.z = fmaf(r[k], sA[k][2], o.z);
        o.w = fmaf(r[k], sA[k][3], o.w);
    }
    if (!valid) o = make_float4(0.f, 0.f, 0.f, 0.f);
    ebS[pos] = o;
}

// ---------------------------------------------------------------------------
// Kernel 6: node GEMM on tensor cores via mma.sync, bf16x3 split. (proven)
// ---------------------------------------------------------------------------
#define LDA 144
#define SM_AHI 0
#define SM_ALO 18432
#define SM_BHI 36864
#define SM_BLO 46080
#define SMEM_BYTES 55296

template <bool RELU>
__global__ void __launch_bounds__(256)
gemm_mma(const float* __restrict__ h,
         const uint4* __restrict__ Bhi,    // [320][64] bf16 (this layer)
         const uint4* __restrict__ Blo,
         const float* __restrict__ bias,
         float* __restrict__ agg) {
    extern __shared__ char smem[];
    const uint32_t sb = smem_u32(smem);
    const int tid = threadIdx.x;
    const int wid = tid >> 5;
    const int lid = tid & 31;
    const int nodeBase = blockIdx.x * 128;
    float* xb = reinterpret_cast<float*>(g_xb4);

    // ---- Convert A rows to bf16 hi/lo into padded smem ----
    if (tid < 128) {
        int n = nodeBase + tid;
        const float4* hp = reinterpret_cast<const float4*>(h + (size_t)n * IN_CH);
        bool valid = (n < N_NODES);
#pragma unroll
        for (int j = 0; j < 8; j++) {
            float f[8];
            if (valid) {
                float4 a = hp[2 * j];
                float4 b = hp[2 * j + 1];
                f[0] = a.x; f[1] = a.y; f[2] = a.z; f[3] = a.w;
                f[4] = b.x; f[5] = b.y; f[6] = b.z; f[7] = b.w;
            } else {
#pragma unroll
                for (int t = 0; t < 8; t++) f[t] = 0.f;
            }
            uint32_t hw[4], lw[4];
#pragma unroll
            for (int q = 0; q < 4; q++) {
                float v0 = f[2 * q], v1 = f[2 * q + 1];
                if (RELU) { v0 = fmaxf(v0, 0.f); v1 = fmaxf(v1, 0.f); }
                __nv_bfloat16 h0 = __float2bfloat16(v0);
                __nv_bfloat16 h1 = __float2bfloat16(v1);
                __nv_bfloat16 l0 = __float2bfloat16(v0 - __bfloat162float(h0));
                __nv_bfloat16 l1 = __float2bfloat16(v1 - __bfloat162float(h1));
                hw[q] = (uint32_t)__bfloat16_as_ushort(h0) |
                        ((uint32_t)__bfloat16_as_ushort(h1) << 16);
                lw[q] = (uint32_t)__bfloat16_as_ushort(l0) |
                        ((uint32_t)__bfloat16_as_ushort(l1) << 16);
            }
            *reinterpret_cast<uint4*>(smem + SM_AHI + tid * LDA + j * 16) =
                make_uint4(hw[0], hw[1], hw[2], hw[3]);
            *reinterpret_cast<uint4*>(smem + SM_ALO + tid * LDA + j * 16) =
                make_uint4(lw[0], lw[1], lw[2], lw[3]);
        }
    }
    __syncthreads();

    // ---- Hoist A fragments ----
    uint32_t ahi[4][4], alo[4][4];
    {
        uint32_t aoff = (uint32_t)(wid * 16 + (lid & 15)) * LDA + ((lid >> 4) << 4);
#pragma unroll
        for (int ks = 0; ks < 4; ks++) {
            ldsm_x4(ahi[ks], sb + SM_AHI + aoff + ks * 32);
            ldsm_x4(alo[ks], sb + SM_ALO + aoff + ks * 32);
        }
    }

    const uint32_t bLane = (uint32_t)((lid & 7) + ((lid >> 4) << 3)) * LDA +
                           (((lid >> 3) & 1) << 4);

#pragma unroll 1
    for (int nt = 0; nt < 5; nt++) {
        if (nt) __syncthreads();
#pragma unroll
        for (int u = tid; u < 512; u += 256) {
            int row = u >> 3;
            int j = u & 7;
            uint32_t off = (uint32_t)row * LDA + j * 16;
            int src = (nt * 64 + row) * 8 + j;
            *reinterpret_cast<uint4*>(smem + SM_BHI + off) = Bhi[src];
            *reinterpret_cast<uint4*>(smem + SM_BLO + off) = Blo[src];
        }
        __syncthreads();

        float acc[8][4];
#pragma unroll
        for (int t = 0; t < 8; t++)
#pragma unroll
            for (int q = 0; q < 4; q++) acc[t][q] = 0.f;

#pragma unroll
        for (int np = 0; np < 4; np++) {
            uint32_t bbase = (uint32_t)(np * 16) * LDA + bLane;
#pragma unroll
            for (int ks = 0; ks < 4; ks++) {
                uint32_t bh[4], bl[4];
                ldsm_x4(bh, sb + SM_BHI + bbase + ks * 32);
                ldsm_x4(bl, sb + SM_BLO + bbase + ks * 32);
                mma16816(acc[np * 2 + 0], ahi[ks], bh + 0);
                mma16816(acc[np * 2 + 1], ahi[ks], bh + 2);
                mma16816(acc[np * 2 + 0], ahi[ks], bl + 0);
                mma16816(acc[np * 2 + 1], ahi[ks], bl + 2);
                mma16816(acc[np * 2 + 0], alo[ks], bh + 0);
                mma16816(acc[np * 2 + 1], alo[ks], bh + 2);
            }
        }

        int r0 = nodeBase + wid * 16 + (lid >> 2);
        int cOff = 2 * (lid & 3);
#pragma unroll
        for (int t = 0; t < 8; t++) {
            int col = nt * 64 + t * 8 + cOff;
            if (nt < 4) {
                if (r0 < N_NODES)
                    *reinterpret_cast<float2*>(xb + (size_t)r0 * XB_COLS + col) =
                        make_float2(acc[t][0], acc[t][1]);
                if (r0 + 8 < N_NODES)
                    *reinterpret_cast<float2*>(xb + (size_t)(r0 + 8) * XB_COLS + col) =
                        make_float2(acc[t][2], acc[t][3]);
            } else {
                int oc = col - 256;
                float b0 = __ldg(bias + oc);
                float b1 = __ldg(bias + oc + 1);
                if (r0 < N_NODES)
                    *reinterpret_cast<float2*>(agg + (size_t)r0 * OUT_CH + oc) =
                        make_float2(acc[t][0] + b0, acc[t][1] + b1);
                if (r0 + 8 < N_NODES)
                    *reinterpret_cast<float2*>(agg + (size_t)(r0 + 8) * OUT_CH + oc) =
                        make_float2(acc[t][2] + b0, acc[t][3] + b1);
            }
        }
    }
}

// ---------------------------------------------------------------------------
// Kernel 7: SRC-RUN edge kernel (proven). Half-warp per SOURCE node.
// ---------------------------------------------------------------------------
__global__ void __launch_bounds__(256)
edge_kernel(const float4* __restrict__ eb,      // src-sorted basis weights
            float* __restrict__ agg) {
    int t = blockIdx.x * blockDim.x + threadIdx.x;
    int n = t >> 4;
    int l = t & 15;
    if (n >= N_NODES) return;

    int start = __ldg(&g_start[n]);
    int end   = __ldg(&g_start[n + 1]);
    if (start >= end) return;

    const float4* xs = g_xb4 + (size_t)n * (XB_COLS / 4);
    float4 v0 = xs[0 * 16 + l];
    float4 v1 = xs[1 * 16 + l];
    float4 v2 = xs[2 * 16 + l];
    float4 v3 = xs[3 * 16 + l];

    for (int e = start; e < end; e++) {
        float4 w = __ldg(eb + e);          // broadcast across 16 lanes
        int dst = __ldg(&g_dp[e].x);

        float4 acc;
        acc.x = fmaf(w.x, v0.x, fmaf(w.y, v1.x, fmaf(w.z, v2.x, w.w * v3.x)));
        acc.y = fmaf(w.x, v0.y, fmaf(w.y, v1.y, fmaf(w.z, v2.y, w.w * v3.y)));
        acc.z = fmaf(w.x, v0.z, fmaf(w.y, v1.z, fmaf(w.z, v2.z, w.w * v3.z)));
        acc.w = fmaf(w.x, v0.w, fmaf(w.y, v1.w, fmaf(w.z, v2.w, w.w * v3.w)));

        float* out = agg + (size_t)dst * OUT_CH + l * 4;
        asm volatile("red.global.add.v4.f32 [%0], {%1, %2, %3, %4};"
                     :: "l"(out), "f"(acc.x), "f"(acc.y), "f"(acc.z), "f"(acc.w)
                     : "memory");
    }
}

// ---------------------------------------------------------------------------
// Launch — forked capture: sort chain on side stream, GEMM chain on default.
// ---------------------------------------------------------------------------
extern "C" void kernel_launch(void* const* d_in, const int* in_sizes, int n_in,
                              void* d_out, int out_size) {
    const float* x        = (const float*)d_in[0];
    const int* ei         = (const int*)d_in[1];     // int32
    const float* ea       = (const float*)d_in[2];
    const float* basis    = (const float*)d_in[3];   // [2, 4, 64, 64]
    const float* att      = (const float*)d_in[4];   // [2, 8, 4]
    const float* root     = (const float*)d_in[5];   // [2, 64, 64]
    const float* bias     = (const float*)d_in[6];   // [2, 64]
    float* out            = (float*)d_out;

    void* p = nullptr;
    cudaGetSymbolAddress(&p, g_agg04);
    float* agg0 = (float*)p;
    cudaGetSymbolAddress(&p, g_ebS0);
    float4* ebS0 = (float4*)p;
    cudaGetSymbolAddress(&p, g_ebS1);
    float4* ebS1 = (float4*)p;
    cudaGetSymbolAddress(&p, g_Bhi4);
    const uint4* Bhi = (const uint4*)p;
    cudaGetSymbolAddress(&p, g_Blo4);
    const uint4* Blo = (const uint4*)p;

    cudaFuncSetAttribute(gemm_mma<false>, cudaFuncAttributeMaxDynamicSharedMemorySize, SMEM_BYTES);
    cudaFuncSetAttribute(gemm_mma<true>,  cudaFuncAttributeMaxDynamicSharedMemorySize, SMEM_BYTES);

    // One-time stream/event setup (host resources only; no device memory)
    static cudaStream_t s2 = nullptr;
    static cudaEvent_t evF = nullptr, evA = nullptr, evB = nullptr;
    if (s2 == nullptr) {
        cudaStreamCreateWithFlags(&s2, cudaStreamNonBlocking);
        cudaEventCreateWithFlags(&evF, cudaEventDisableTiming);
        cudaEventCreateWithFlags(&evA, cudaEventDisableTiming);
        cudaEventCreateWithFlags(&evB, cudaEventDisableTiming);
    }

    const int eBlocks     = (N_EDGES + 255) / 256;          // 3125
    const int gemmBlocks  = (N_NODES + 127) / 128;          // 391
    const int nodeBlocks  = (N_NODES * 16 + 255) / 256;     // 3125
    const int bprepBlocks = (2 * GEMM_N * 64 + 255) / 256;  // 160

    const float* att1  = att + N_REL * N_BASES;
    const float* bias1 = bias + OUT_CH;
    const int layerStride = GEMM_N * 64 * 2 / 16;   // uint4 per layer

    // ---- Fork: side stream joins the capture ----
    cudaEventRecord(evF, 0);
    cudaStreamWaitEvent(s2, evF, 0);

    // Side stream: counting sort + fused layer-0 eb scatter, then layer-1 eb
    count_kernel<<<eBlocks, 256, 0, s2>>>(ei);
    scan1_kernel<<<NBLK, 256, 0, s2>>>();
    scan3_kernel<<<NBLK, 256, 0, s2>>>();
    scatter_eb0_kernel<<<eBlocks, 256, 0, s2>>>(ei, ea, att);
    cudaEventRecord(evA, s2);
    eb_gather_kernel<<<eBlocks, 256, 0, s2>>>(ea, att1, ebS1);   // overlaps edge0
    cudaEventRecord(evB, s2);

    // Default stream: weight prep + layer-0 GEMM (independent of sort chain)
    bprep_kernel<<<bprepBlocks, 256>>>(basis, root);
    gemm_mma<false><<<gemmBlocks, 256, SMEM_BYTES>>>(x, Bhi, Blo, bias, agg0);

    // Join A: edge0 needs sort results + gemm0 output
    cudaStreamWaitEvent(0, evA, 0);
    edge_kernel<<<nodeBlocks, 256>>>(ebS0, agg0);

    // Layer 1
    gemm_mma<true><<<gemmBlocks, 256, SMEM_BYTES>>>(agg0, Bhi + layerStride,
                                                    Blo + layerStride, bias1, out);
    cudaStreamWaitEvent(0, evB, 0);
    edge_kernel<<<nodeBlocks, 256>>>(ebS1, out);
}